// round 8
// baseline (speedup 1.0000x reference)
#include <cuda_runtime.h>
#include <cuda_fp16.h>
#include <math.h>
#include <stdint.h>

#define NROWS 4096
#define TWO_N 8192
#define D 128
#define NTILE 64
#define NJOBS 2080                  // 64*65/2 triangle tiles
#define GRID_MAIN 148
#define K2C 14.4269504088896340f    // 10 / ln(2)
#define PSC 3.798282565009841f      // sqrt(10/ln(2)) pre-scale

// ---------------- device scratch (allocation-free) ----------------
__device__ __half         g_h[TWO_N * D];      // sqrt(K2C)-scaled normalized reps, fp16
__device__ float          g_pos[TWO_N];
__device__ float          g_part[NTILE * NTILE * 128];
__device__ float          g_bsum[32];
__device__ unsigned int   g_bar1, g_bar2, g_bar3;   // zero-init; reset each run

// ---------------- smem map (dynamic) ----------------
#define SM_A      0
#define SM_B(s)   (32768 + (s) * 32768)
#define SM_ROWRED 98304
#define SM_COLRED 100352
// pad request to 128KB: forces 1 CTA/SM -> all 148 CTAs co-resident (spin-barrier safe)
#define SMEM_BYTES 131072

// ---------------- helpers ----------------
__device__ __forceinline__ uint32_t smem_u32(const void* p) {
    uint32_t a;
    asm("{ .reg .u64 t; cvta.to.shared.u64 t, %1; cvt.u32.u64 %0, t; }" : "=r"(a) : "l"(p));
    return a;
}
__device__ __forceinline__ float ex2f(float x) {
    float r; asm("ex2.approx.ftz.f32 %0, %1;" : "=f"(r) : "f"(x)); return r;
}
__device__ __forceinline__ void ldsm4(uint32_t* r, uint32_t addr) {
    asm volatile("ldmatrix.sync.aligned.m8n8.x4.shared.b16 {%0,%1,%2,%3}, [%4];"
                 : "=r"(r[0]), "=r"(r[1]), "=r"(r[2]), "=r"(r[3]) : "r"(addr));
}
__device__ __forceinline__ void mma_fp16(float* d, const uint32_t* a, uint32_t b0, uint32_t b1) {
    asm volatile("mma.sync.aligned.m16n8k16.row.col.f32.f16.f16.f32 "
                 "{%0,%1,%2,%3}, {%4,%5,%6,%7}, {%8,%9}, {%0,%1,%2,%3};"
                 : "+f"(d[0]), "+f"(d[1]), "+f"(d[2]), "+f"(d[3])
                 : "r"(a[0]), "r"(a[1]), "r"(a[2]), "r"(a[3]), "r"(b0), "r"(b1));
}
#define CP_ASYNC16(sa, ga) \
    asm volatile("cp.async.cg.shared.global [%0], [%1], 16;" :: "r"(sa), "l"(ga))
#define CP_COMMIT() asm volatile("cp.async.commit_group;" ::: "memory")
#define CP_WAIT1()  asm volatile("cp.async.wait_group 1;" ::: "memory")

__device__ __forceinline__ void job_ij(int g, int& I, int& J) {
    int i = 0, off = 0;
    while (off + (NTILE - i) <= g) { off += NTILE - i; i++; }
    I = i; J = i + (g - off);
}
__device__ __forceinline__ void job_adv(int& I, int& J) {
    if (++J == NTILE) { ++I; J = I; }
}

// device-wide spin barrier (all 148 CTAs resident; tid 0 spins, smem flag releases)
__device__ __forceinline__ void grid_barrier(unsigned int* ctr, char* sm_flag) {
    __syncthreads();
    if (threadIdx.x == 0) {
        __threadfence();
        atomicAdd(ctr, 1u);
        while (atomicAdd(ctr, 0u) < GRID_MAIN) { }
        __threadfence();
    }
    __syncthreads();
    (void)sm_flag;
}

// ---------------- tile loaders (XOR-swizzled 16B chunks, 256B rows) ----------------
__device__ __forceinline__ void load_B_async(uint32_t sb, uint32_t off, int rowBase, int t) {
    #pragma unroll
    for (int rep = 0; rep < 8; rep++) {
        int idx = rep * 256 + t;
        int row = idx >> 4, ch = idx & 15;
        uint32_t so = off + (uint32_t)(row * 256) + ((uint32_t)(ch ^ (row & 7)) << 4);
        CP_ASYNC16(sb + so, g_h + (size_t)(rowBase + row) * D + ch * 8);
    }
}
__device__ __forceinline__ void load_A_plain(char* sm, int rowBase, int t) {
    #pragma unroll
    for (int rep = 0; rep < 8; rep++) {
        int idx = rep * 256 + t;
        int row = idx >> 4, ch = idx & 15;
        uint32_t so = (uint32_t)(row * 256) + ((uint32_t)(ch ^ (row & 7)) << 4);
        *(uint4*)(sm + SM_A + so) = *(const uint4*)(g_h + (size_t)(rowBase + row) * D + ch * 8);
    }
}

// ---------------------------------------------------------------------------
// Fused kernel: prep -> barrier -> triangle fp16 GEMM + exp sums -> barrier
//               -> distributed tail -> last CTA writes loss + resets counters.
// ---------------------------------------------------------------------------
__global__ __launch_bounds__(256, 1)
void k_all(const float* __restrict__ zi, const float* __restrict__ zj,
           float* __restrict__ out) {
    extern __shared__ char sm[];
    const uint32_t sb = smem_u32(sm);
    const int t = threadIdx.x, lane = t & 31, wid = t >> 5;
    const int warpM = wid >> 2, warpN = wid & 3;

    // ---------------- Phase 1: prep (pairs striped over 1184 warps) ----------------
    for (int p = blockIdx.x * 8 + wid; p < NROWS; p += GRID_MAIN * 8) {
        float4 a = ((const float4*)(zi + (size_t)p * D))[lane];
        float4 b = ((const float4*)(zj + (size_t)p * D))[lane];
        float sa = a.x*a.x + a.y*a.y + a.z*a.z + a.w*a.w;
        float sbn = b.x*b.x + b.y*b.y + b.z*b.z + b.w*b.w;
        float dp = a.x*b.x + a.y*b.y + a.z*b.z + a.w*b.w;
        #pragma unroll
        for (int o = 16; o; o >>= 1) {
            sa  += __shfl_xor_sync(0xffffffffu, sa, o);
            sbn += __shfl_xor_sync(0xffffffffu, sbn, o);
            dp  += __shfl_xor_sync(0xffffffffu, dp, o);
        }
        float ia = 1.0f / fmaxf(sqrtf(sa), 1e-8f);
        float ib = 1.0f / fmaxf(sqrtf(sbn), 1e-8f);
        if (lane == 0) {
            float pos = dp * ia * ib;
            g_pos[p] = pos;
            g_pos[p + NROWS] = pos;
        }
        float fa = ia * PSC, fb = ib * PSC;
        __half ha[4], hb[4];
        ha[0] = __float2half(a.x*fa); ha[1] = __float2half(a.y*fa);
        ha[2] = __float2half(a.z*fa); ha[3] = __float2half(a.w*fa);
        hb[0] = __float2half(b.x*fb); hb[1] = __float2half(b.y*fb);
        hb[2] = __float2half(b.z*fb); hb[3] = __float2half(b.w*fb);
        *(uint2*)(g_h + (size_t)p * D + lane * 4)           = *(uint2*)ha;
        *(uint2*)(g_h + (size_t)(p + NROWS) * D + lane * 4) = *(uint2*)hb;
    }

    grid_barrier(&g_bar1, sm);

    // ---------------- Phase 2: triangle GEMM + exp row/col sums ----------------
    {
        const int jb = (int)(((long)blockIdx.x * NJOBS) / GRID_MAIN);
        const int je = (int)(((long)(blockIdx.x + 1) * NJOBS) / GRID_MAIN);
        const int njobs = je - jb;

        int Ic, Jc; job_ij(jb, Ic, Jc);
        int Ip = Ic, Jp = Jc;

        load_B_async(sb, SM_B(0), Jp * 128, t); CP_COMMIT(); job_adv(Ip, Jp);
        load_B_async(sb, SM_B(1), Jp * 128, t); CP_COMMIT(); job_adv(Ip, Jp);

        const int r7   = lane & 7;
        const int rowA = (lane & 7) + ((lane >> 3) & 1) * 8;  const int c4A = lane >> 4;
        const int rowB = (lane & 7) + ((lane >> 4) << 3);     const int c4B = (lane >> 3) & 1;

        uint32_t aRow[4];
        #pragma unroll
        for (int mt = 0; mt < 4; mt++)
            aRow[mt] = sb + SM_A + (uint32_t)((warpM * 64 + mt * 16 + rowA) * 256);
        uint32_t bRow[2];
        #pragma unroll
        for (int g = 0; g < 2; g++) bRow[g] = (uint32_t)((warpN * 32 + g * 16 + rowB) * 256);

        float* rowred = (float*)(sm + SM_ROWRED);
        float* colred = (float*)(sm + SM_COLRED);
        int Ia = -1;

        for (int jj = 0; jj < njobs; jj++) {
            if (Ic != Ia) { load_A_plain(sm, Ic * 128, t); Ia = Ic; }
            CP_WAIT1();
            __syncthreads();

            const uint32_t bBase = sb + SM_B(jj & 1);

            float d[4][4][4];
            #pragma unroll
            for (int mt = 0; mt < 4; mt++)
                #pragma unroll
                for (int nt = 0; nt < 4; nt++)
                    #pragma unroll
                    for (int q = 0; q < 4; q++) d[mt][nt][q] = -K2C;  // folds the -10 shift

            #pragma unroll
            for (int ks = 0; ks < 8; ks++) {
                uint32_t ah[4][4], bh[8];
                const uint32_t offA = (uint32_t)(((2 * ks + c4A) ^ r7) << 4);
                const uint32_t offB = (uint32_t)(((2 * ks + c4B) ^ r7) << 4);
                #pragma unroll
                for (int mt = 0; mt < 4; mt++) ldsm4(ah[mt], aRow[mt] + offA);
                #pragma unroll
                for (int g = 0; g < 2; g++) ldsm4(bh + g * 4, bBase + bRow[g] + offB);
                #pragma unroll
                for (int mt = 0; mt < 4; mt++)
                    #pragma unroll
                    for (int nt = 0; nt < 4; nt++)
                        mma_fp16(d[mt][nt], ah[mt], bh[nt * 2], bh[nt * 2 + 1]);
            }
            __syncthreads();
            if (jj + 2 < njobs) {
                load_B_async(sb, SM_B(jj & 1), Jp * 128, t); CP_COMMIT(); job_adv(Ip, Jp);
            } else {
                CP_COMMIT();
            }

            // ---- epilogue: exp + row sums + col sums ----
            float rs[8], cc[8];
            #pragma unroll
            for (int u = 0; u < 8; u++) { rs[u] = 0.0f; cc[u] = 0.0f; }
            #pragma unroll
            for (int mt = 0; mt < 4; mt++) {
                #pragma unroll
                for (int nt = 0; nt < 4; nt++) {
                    float e0 = ex2f(d[mt][nt][0]);
                    float e1 = ex2f(d[mt][nt][1]);
                    float e2 = ex2f(d[mt][nt][2]);
                    float e3 = ex2f(d[mt][nt][3]);
                    rs[mt * 2 + 0] += e0 + e1;
                    rs[mt * 2 + 1] += e2 + e3;
                    cc[nt * 2 + 0] += e0 + e2;
                    cc[nt * 2 + 1] += e1 + e3;
                }
            }
            #pragma unroll
            for (int u = 0; u < 8; u++) {
                float v = rs[u];
                v += __shfl_xor_sync(0xffffffffu, v, 1);
                v += __shfl_xor_sync(0xffffffffu, v, 2);
                if ((lane & 3) == 0) {
                    int r = warpM * 64 + (u >> 1) * 16 + (u & 1) * 8 + (lane >> 2);
                    rowred[r * 4 + warpN] = v;
                }
            }
            #pragma unroll
            for (int u = 0; u < 8; u++) {
                float v = cc[u];
                v += __shfl_xor_sync(0xffffffffu, v, 4);
                v += __shfl_xor_sync(0xffffffffu, v, 8);
                v += __shfl_xor_sync(0xffffffffu, v, 16);
                if (lane < 4) {
                    int c = warpN * 32 + (u >> 1) * 8 + (lane & 3) * 2 + (u & 1);
                    colred[c * 2 + warpM] = v;
                }
            }
            __syncthreads();
            if (t < 128) {
                float s = rowred[t * 4] + rowred[t * 4 + 1] + rowred[t * 4 + 2] + rowred[t * 4 + 3];
                g_part[(size_t)((Ic << 6) + Jc) * 128 + t] = s;
            } else if (Jc > Ic) {
                int c = t - 128;
                g_part[(size_t)((Jc << 6) + Ic) * 128 + c] = colred[c * 2] + colred[c * 2 + 1];
            }
            __syncthreads();
            job_adv(Ic, Jc);
        }
    }

    grid_barrier(&g_bar2, sm);

    // ---------------- Phase 3: distributed tail ----------------
    // First 32 CTAs: per-row loss for 256 rows each; block-reduce to g_bsum.
    if (blockIdx.x < 32) {
        float* red = (float*)(sm + SM_ROWRED);
        int r = blockIdx.x * 256 + t;
        int I = r >> 7, rr = r & 127;
        float S = 0.0f;
        const float* base = g_part + (size_t)(I << 6) * 128 + rr;
        #pragma unroll 8
        for (int J = 0; J < NTILE; J++) S += base[(size_t)J * 128];
        float p = g_pos[r];
        float Sf = S + expf(fmaf(10.0f, p, -10.0f));
        red[t] = logf(Sf) + 10.0f - 10.0f * p;
        __syncthreads();
        for (int s = 128; s; s >>= 1) {
            if (t < s) red[t] += red[t + s];
            __syncthreads();
        }
        if (t == 0) g_bsum[blockIdx.x] = red[0];
    }

    // last CTA to arrive folds the 32 block sums, writes out, resets counters
    __syncthreads();
    if (t == 0) {
        __threadfence();
        unsigned int done = atomicAdd(&g_bar3, 1u);
        if (done == GRID_MAIN - 1) {
            float acc = 0.0f;
            #pragma unroll
            for (int b = 0; b < 32; b++) acc += ((volatile float*)g_bsum)[b];
            out[0] = acc * (1.0f / (float)TWO_N);
            g_bar1 = 0; g_bar2 = 0; g_bar3 = 0;   // reset for next graph replay
            __threadfence();
        }
    }
}

// ---------------------------------------------------------------------------
extern "C" void kernel_launch(void* const* d_in, const int* in_sizes, int n_in,
                              void* d_out, int out_size) {
    const float* zi = (const float*)d_in[0];
    const float* zj = (const float*)d_in[1];
    float* out = (float*)d_out;

    cudaFuncSetAttribute(k_all, cudaFuncAttributeMaxDynamicSharedMemorySize, SMEM_BYTES);
    k_all<<<GRID_MAIN, 256, SMEM_BYTES>>>(zi, zj, out);
}